// round 5
// baseline (speedup 1.0000x reference)
#include <cuda_runtime.h>
#include <math.h>

#define DIMV       512
#define HEADS      8
#define DIM_KEY    32
#define NUM_KEYS   256
#define TOPK       16
#define TOKENS     1024
#define FULLMASK   0xffffffffu

// scratch (device globals; no allocs)
__device__ float g_q[TOKENS * DIMV];                    // 2 MB
__device__ float g_sim[HEADS * TOKENS * NUM_KEYS];      // 8 MB
__device__ float g_wdT[DIMV * NUM_KEYS];                // 512 KB
__device__ float g_D[TOKENS * NUM_KEYS];                // 1 MB
__device__ float g_S[TOKENS * NUM_KEYS];                // 1 MB

// ---------------------------------------------------------------------------
// Register-pipelined SGEMM block, 32x64 tile, 256 threads, 2x4 per thread.
// BK=16, double-buffered smem, one __syncthreads per k-tile.
// smem: As[2][16][36] then Bs[2][16][64]  (12800 B)
// ---------------------------------------------------------------------------
#define GEMM_SMEM_BYTES (2*16*36*4 + 2*16*64*4)

template<int N, int K, bool SCALE>
__device__ __forceinline__ void sgemm_block32(
    const float* __restrict__ A, const float* __restrict__ B,
    float* __restrict__ C, int m0, int n0, char* smem_raw)
{
    typedef float AsT[16][36];
    typedef float BsT[16][64];
    AsT* As = (AsT*)smem_raw;
    BsT* Bs = (BsT*)(smem_raw + 2 * 16 * 36 * 4);

    int tid = threadIdx.x;
    int tx = tid & 15;
    int ty = tid >> 4;

    float acc[2][4];
#pragma unroll
    for (int i = 0; i < 2; i++)
#pragma unroll
        for (int j = 0; j < 4; j++) acc[i][j] = 0.0f;

    const int arow = tid >> 3;          // 0..31
    const int akq  = (tid & 7) * 2;     // 0..14 step 2
    const int bkrow = tid >> 4;         // 0..15
    const int bnq   = (tid & 15) * 4;   // 0..60 step 4

    float2 arg;
    float4 brg;

    arg = *reinterpret_cast<const float2*>(&A[(size_t)(m0 + arow) * K + akq]);
    brg = *reinterpret_cast<const float4*>(&B[(size_t)bkrow * N + n0 + bnq]);

    int buf = 0;
    const int NT = K / 16;
#pragma unroll 1
    for (int kt = 0; kt < NT; kt++) {
        As[buf][akq + 0][arow] = arg.x;
        As[buf][akq + 1][arow] = arg.y;
        *reinterpret_cast<float4*>(&Bs[buf][bkrow][bnq]) = brg;
        __syncthreads();

        if (kt + 1 < NT) {
            int k0 = (kt + 1) * 16;
            arg = *reinterpret_cast<const float2*>(
                &A[(size_t)(m0 + arow) * K + k0 + akq]);
            brg = *reinterpret_cast<const float4*>(
                &B[(size_t)(k0 + bkrow) * N + n0 + bnq]);
        }

        float2 ac = *reinterpret_cast<const float2*>(&As[buf][0][ty * 2]);
        float4 bc = *reinterpret_cast<const float4*>(&Bs[buf][0][tx * 4]);
#pragma unroll
        for (int k = 0; k < 16; k++) {
            float2 an; float4 bn;
            if (k < 15) {
                an = *reinterpret_cast<const float2*>(&As[buf][k + 1][ty * 2]);
                bn = *reinterpret_cast<const float4*>(&Bs[buf][k + 1][tx * 4]);
            }
            acc[0][0] += ac.x * bc.x; acc[0][1] += ac.x * bc.y;
            acc[0][2] += ac.x * bc.z; acc[0][3] += ac.x * bc.w;
            acc[1][0] += ac.y * bc.x; acc[1][1] += ac.y * bc.y;
            acc[1][2] += ac.y * bc.z; acc[1][3] += ac.y * bc.w;
            if (k < 15) { ac = an; bc = bn; }
        }
        buf ^= 1;
    }

    const float scale = SCALE ? 0.99999500003749981f : 1.0f;
#pragma unroll
    for (int i = 0; i < 2; i++) {
        int row = m0 + ty * 2 + i;
        float4 f;
        f.x = acc[i][0] * scale; f.y = acc[i][1] * scale;
        f.z = acc[i][2] * scale; f.w = acc[i][3] * scale;
        *reinterpret_cast<float4*>(&C[(size_t)row * N + n0 + tx * 4]) = f;
    }
}

// ---------------------------------------------------------------------------
// K1: G1 (q = x @ w_q, scaled) on blocks 0..255; transpose wdown on 256..383.
// ---------------------------------------------------------------------------
__global__ void __launch_bounds__(256)
k1_fused(const float* __restrict__ x, const float* __restrict__ wq,
         const float* __restrict__ wdown)
{
    __shared__ __align__(16) char smem[GEMM_SMEM_BYTES];
    int bid = blockIdx.x;
    if (bid < 256) {
        int mb = bid >> 3, nb = bid & 7;
        sgemm_block32<DIMV, DIMV, true>(x, wq, g_q, mb * 32, nb * 64, smem);
    } else {
        int b = bid - 256;
        int d0 = (b & 15) * 32;
        int e0 = (b >> 4) * 32;
        float (*t)[33] = (float(*)[33])smem;
        int tx = threadIdx.x & 31, ty = threadIdx.x >> 5;  // 32 x 8
#pragma unroll
        for (int i = 0; i < 4; i++)
            t[ty + i * 8][tx] = wdown[(size_t)(e0 + ty + i * 8) * DIMV + d0 + tx];
        __syncthreads();
#pragma unroll
        for (int i = 0; i < 4; i++)
            g_wdT[(size_t)(d0 + ty + i * 8) * NUM_KEYS + e0 + tx] = t[tx][ty + i * 8];
    }
}

// ---------------------------------------------------------------------------
// K2: G2 (D = q @ wdT) on blocks 0..127; sim on 128..255.
// ---------------------------------------------------------------------------
__global__ void __launch_bounds__(256)
k2_fused(const float* __restrict__ keys)
{
    __shared__ __align__(16) char smem[DIM_KEY * NUM_KEYS * 4 + DIM_KEY * 64 * 4];
    int bid = blockIdx.x;
    int tid = threadIdx.x;

    if (bid < 128) {
        // G2: M=1024 (32 m-tiles), N=256 (4 n-tiles)
        int mb = bid >> 2, nb = bid & 3;
        sgemm_block32<NUM_KEYS, DIMV, false>(g_q, g_wdT, g_D, mb * 32, nb * 64, smem);
        return;
    }

    // sim
    int b = bid - 128;
    int t0 = (b & 15) * 64;
    int h = b >> 4;

    float (*Ks)[NUM_KEYS] = (float(*)[NUM_KEYS])smem;
    float (*Qs)[64] = (float(*)[64])(smem + DIM_KEY * NUM_KEYS * 4);

    {
        const float4* kp = reinterpret_cast<const float4*>(
            keys + (size_t)((h * NUM_KEYS + tid) * 2) * DIM_KEY);
#pragma unroll
        for (int i = 0; i < 8; i++) {
            float4 f = kp[i];
            Ks[4 * i + 0][tid] = f.x;
            Ks[4 * i + 1][tid] = f.y;
            Ks[4 * i + 2][tid] = f.z;
            Ks[4 * i + 3][tid] = f.w;
        }
    }
    {
        int tl = tid & 63;
        int d0 = (tid >> 6) * 8;
        const float* qp = g_q + (size_t)(t0 + tl) * DIMV + h * DIM_KEY + d0;
        float4 f0 = *reinterpret_cast<const float4*>(qp);
        float4 f1 = *reinterpret_cast<const float4*>(qp + 4);
        Qs[d0 + 0][tl] = f0.x; Qs[d0 + 1][tl] = f0.y;
        Qs[d0 + 2][tl] = f0.z; Qs[d0 + 3][tl] = f0.w;
        Qs[d0 + 4][tl] = f1.x; Qs[d0 + 5][tl] = f1.y;
        Qs[d0 + 6][tl] = f1.z; Qs[d0 + 7][tl] = f1.w;
    }
    __syncthreads();

    int kg = tid & 15;
    int tg = tid >> 4;
    float acc[4][16];
#pragma unroll
    for (int i = 0; i < 4; i++)
#pragma unroll
        for (int j = 0; j < 16; j++) acc[i][j] = 0.0f;

#pragma unroll
    for (int d = 0; d < DIM_KEY; d++) {
        float4 qv = *reinterpret_cast<const float4*>(&Qs[d][tg * 4]);
        float q4[4] = {qv.x, qv.y, qv.z, qv.w};
        float kv[16];
#pragma unroll
        for (int jj = 0; jj < 4; jj++) {
            float4 kk = *reinterpret_cast<const float4*>(&Ks[d][kg * 16 + jj * 4]);
            kv[jj * 4 + 0] = kk.x; kv[jj * 4 + 1] = kk.y;
            kv[jj * 4 + 2] = kk.z; kv[jj * 4 + 3] = kk.w;
        }
#pragma unroll
        for (int i = 0; i < 4; i++)
#pragma unroll
            for (int j = 0; j < 16; j++) acc[i][j] += q4[i] * kv[j];
    }

#pragma unroll
    for (int i = 0; i < 4; i++) {
        int t = t0 + tg * 4 + i;
        float* op = g_sim + ((size_t)h * TOKENS + t) * NUM_KEYS + kg * 16;
#pragma unroll
        for (int jj = 0; jj < 4; jj++) {
            float4 f;
            f.x = acc[i][jj * 4 + 0]; f.y = acc[i][jj * 4 + 1];
            f.z = acc[i][jj * 4 + 2]; f.w = acc[i][jj * 4 + 3];
            *reinterpret_cast<float4*>(op + jj * 4) = f;
        }
    }
}

// ---------------------------------------------------------------------------
// K3: selection (deterministic cross-head merge, no atomics).
// ---------------------------------------------------------------------------
__device__ __forceinline__ float gelu_tanh(float x) {
    float x3 = x * x * x;
    float t = tanhf(0.7978845608028654f * (x + 0.044715f * x3));
    return 0.5f * x * (1.0f + t);
}

__device__ __forceinline__ void warp_top16(float* val, int lane,
                                           float* out_v, int* out_i)
{
#pragma unroll
    for (int r = 0; r < TOPK; r++) {
        float bv = val[0]; int bs = 0;
#pragma unroll
        for (int s = 1; s < 8; s++)
            if (val[s] > bv) { bv = val[s]; bs = s; }
        int bp = lane + (bs << 5);
#pragma unroll
        for (int off = 16; off > 0; off >>= 1) {
            float ov = __shfl_xor_sync(FULLMASK, bv, off);
            int   op = __shfl_xor_sync(FULLMASK, bp, off);
            if (ov > bv || (ov == bv && op < bp)) { bv = ov; bp = op; }
        }
        out_v[r] = bv;
        out_i[r] = bp;
        if ((bp & 31) == lane) {
            int ws = bp >> 5;
#pragma unroll
            for (int s = 0; s < 8; s++)
                if (s == ws) val[s] = -INFINITY;
        }
    }
}

__global__ void __launch_bounds__(256) select_kernel()
{
    int t = blockIdx.x;
    int tid = threadIdx.x;
    int w = tid >> 5;
    int lane = tid & 31;

    __shared__ float v0s[HEADS][TOPK];
    __shared__ float i0s[HEADS][TOPK];
    __shared__ int   pk_all[HEADS * TOPK];   // 128
    __shared__ float g_all[HEADS * TOPK];

    float val[8];
    {
        const float* simrow = g_sim + ((size_t)w * TOKENS + t) * NUM_KEYS;
#pragma unroll
        for (int s = 0; s < 8; s++)
            val[s] = simrow[lane + (s << 5)];
    }

    float v0[TOPK]; int i0[TOPK];
    warp_top16(val, lane, v0, i0);
    if (lane == 0) {
#pragma unroll
        for (int r = 0; r < TOPK; r++) {
            v0s[w][r] = v0[r];
            i0s[w][r] = (float)i0[r];
        }
    }
    __syncwarp();

    float val2[8];
#pragma unroll
    for (int s = 0; s < 8; s++) {
        int p = lane + (s << 5);
        val2[s] = v0s[w][p >> 4] + i0s[w][p & 15];
    }

    float scf[TOPK]; int pk[TOPK];
    warp_top16(val2, lane, scf, pk);

    float myscf = -INFINITY; int mypk = 0;
#pragma unroll
    for (int r = 0; r < TOPK; r++)
        if (lane == r) { myscf = scf[r]; mypk = pk[r]; }

    float m = scf[0];
#pragma unroll
    for (int r = 1; r < TOPK; r++) m = fmaxf(m, scf[r]);
    float mye = expf(myscf - m);
    float esum = mye;
#pragma unroll
    for (int off = 16; off > 0; off >>= 1)
        esum += __shfl_xor_sync(FULLMASK, esum, off);

    if (lane < TOPK) {
        float dv = g_D[(size_t)t * NUM_KEYS + mypk];
        float g = gelu_tanh(dv) * (mye / esum);
        pk_all[w * TOPK + lane] = mypk;
        g_all[w * TOPK + lane] = g;
    }
    __syncthreads();

    // deterministic merge: thread e sums all entries with pk == e (fixed order)
    float s = 0.0f;
#pragma unroll
    for (int i = 0; i < HEADS * TOPK; i++) {
        s += (pk_all[i] == tid) ? g_all[i] : 0.0f;
    }
    g_S[(size_t)t * NUM_KEYS + tid] = s;
}

// ---------------------------------------------------------------------------
// K4: out = S @ wup[:256]
// ---------------------------------------------------------------------------
__global__ void __launch_bounds__(256)
k4_gemm(const float* __restrict__ wup, float* __restrict__ out)
{
    __shared__ __align__(16) char smem[GEMM_SMEM_BYTES];
    int bid = blockIdx.x;
    int mb = bid >> 3, nb = bid & 7;
    sgemm_block32<DIMV, NUM_KEYS, false>(g_S, wup, out, mb * 32, nb * 64, smem);
}

// ---------------------------------------------------------------------------
extern "C" void kernel_launch(void* const* d_in, const int* in_sizes, int n_in,
                              void* d_out, int out_size)
{
    const float* x     = (const float*)d_in[0];
    const float* w_q   = (const float*)d_in[1];
    const float* keys  = (const float*)d_in[2];
    const float* wdown = (const float*)d_in[3];
    const float* wup   = (const float*)d_in[4];
    float* out = (float*)d_out;

    k1_fused<<<384, 256>>>(x, w_q, wdown);
    k2_fused<<<256, 256>>>(keys);
    select_kernel<<<TOKENS, 256>>>();
    k4_gemm<<<256, 256>>>(wup, out);
}

// round 6
// speedup vs baseline: 1.0910x; 1.0910x over previous
#include <cuda_runtime.h>
#include <math.h>

#define DIMV       512
#define HEADS      8
#define DIM_KEY    32
#define NUM_KEYS   256
#define TOPK       16
#define TOKENS     1024
#define FULLMASK   0xffffffffu

// scratch (device globals; no allocs)
__device__ float g_q[TOKENS * DIMV];                    // 2 MB
__device__ float g_sim[HEADS * TOKENS * NUM_KEYS];      // 8 MB
__device__ float g_wdT[DIMV * NUM_KEYS];                // 512 KB
__device__ float g_D[TOKENS * NUM_KEYS];                // 1 MB
__device__ float g_S[TOKENS * NUM_KEYS];                // 1 MB

// ---------------------------------------------------------------------------
// SGEMM block: 32x64 C-tile, 128 threads, 4x4 per thread, BK=16,
// double-buffered smem, register-pipelined fragments.
// smem: As[2][16][36], Bs[2][16][64]  -> 12800 B
// ---------------------------------------------------------------------------
#define GEMM_SMEM_BYTES (2*16*36*4 + 2*16*64*4)

template<int N, int K, bool SCALE>
__device__ __forceinline__ void sgemm32x64(
    const float* __restrict__ A, const float* __restrict__ B,
    float* __restrict__ C, int m0, int n0, char* smem_raw)
{
    typedef float AsT[16][36];
    typedef float BsT[16][64];
    AsT* As = (AsT*)smem_raw;
    BsT* Bs = (BsT*)(smem_raw + 2 * 16 * 36 * 4);

    const int tid = threadIdx.x;          // 0..127
    const int tx = tid & 15;              // n group (4 cols)
    const int ty = tid >> 4;              // m group (4 rows), 0..7

    // load mappings
    const int arow = tid >> 2;            // 0..31
    const int akq  = (tid & 3) * 4;       // 0,4,8,12
    const int bkr  = tid >> 4;            // 0..7  (rows bkr and bkr+8)
    const int bnq  = (tid & 15) * 4;      // 0..60

    float acc[4][4];
#pragma unroll
    for (int i = 0; i < 4; i++)
#pragma unroll
        for (int j = 0; j < 4; j++) acc[i][j] = 0.0f;

    float4 arg, brg0, brg1;
    arg  = *reinterpret_cast<const float4*>(&A[(size_t)(m0 + arow) * K + akq]);
    brg0 = *reinterpret_cast<const float4*>(&B[(size_t)bkr * N + n0 + bnq]);
    brg1 = *reinterpret_cast<const float4*>(&B[(size_t)(bkr + 8) * N + n0 + bnq]);

    int buf = 0;
    const int NT = K / 16;
#pragma unroll 1
    for (int kt = 0; kt < NT; kt++) {
        As[buf][akq + 0][arow] = arg.x;
        As[buf][akq + 1][arow] = arg.y;
        As[buf][akq + 2][arow] = arg.z;
        As[buf][akq + 3][arow] = arg.w;
        *reinterpret_cast<float4*>(&Bs[buf][bkr][bnq])     = brg0;
        *reinterpret_cast<float4*>(&Bs[buf][bkr + 8][bnq]) = brg1;
        __syncthreads();

        if (kt + 1 < NT) {
            int k0 = (kt + 1) * 16;
            arg  = *reinterpret_cast<const float4*>(
                &A[(size_t)(m0 + arow) * K + k0 + akq]);
            brg0 = *reinterpret_cast<const float4*>(
                &B[(size_t)(k0 + bkr) * N + n0 + bnq]);
            brg1 = *reinterpret_cast<const float4*>(
                &B[(size_t)(k0 + bkr + 8) * N + n0 + bnq]);
        }

        float4 ac = *reinterpret_cast<const float4*>(&As[buf][0][ty * 4]);
        float4 bc = *reinterpret_cast<const float4*>(&Bs[buf][0][tx * 4]);
#pragma unroll
        for (int k = 0; k < 16; k++) {
            float4 an, bn;
            if (k < 15) {
                an = *reinterpret_cast<const float4*>(&As[buf][k + 1][ty * 4]);
                bn = *reinterpret_cast<const float4*>(&Bs[buf][k + 1][tx * 4]);
            }
            acc[0][0] += ac.x * bc.x; acc[0][1] += ac.x * bc.y;
            acc[0][2] += ac.x * bc.z; acc[0][3] += ac.x * bc.w;
            acc[1][0] += ac.y * bc.x; acc[1][1] += ac.y * bc.y;
            acc[1][2] += ac.y * bc.z; acc[1][3] += ac.y * bc.w;
            acc[2][0] += ac.z * bc.x; acc[2][1] += ac.z * bc.y;
            acc[2][2] += ac.z * bc.z; acc[2][3] += ac.z * bc.w;
            acc[3][0] += ac.w * bc.x; acc[3][1] += ac.w * bc.y;
            acc[3][2] += ac.w * bc.z; acc[3][3] += ac.w * bc.w;
            if (k < 15) { ac = an; bc = bn; }
        }
        buf ^= 1;
    }

    const float scale = SCALE ? 0.99999500003749981f : 1.0f;
#pragma unroll
    for (int i = 0; i < 4; i++) {
        int row = m0 + ty * 4 + i;
        float4 f;
        f.x = acc[i][0] * scale; f.y = acc[i][1] * scale;
        f.z = acc[i][2] * scale; f.w = acc[i][3] * scale;
        *reinterpret_cast<float4*>(&C[(size_t)row * N + n0 + tx * 4]) = f;
    }
}

// ---------------------------------------------------------------------------
// K1: blocks 0..255 -> G1 (q = x @ w_q, scaled); 256..383 -> transpose wdown.
// ---------------------------------------------------------------------------
__global__ void __launch_bounds__(128)
k1_fused(const float* __restrict__ x, const float* __restrict__ wq,
         const float* __restrict__ wdown)
{
    __shared__ __align__(16) char smem[GEMM_SMEM_BYTES];
    int bid = blockIdx.x;
    if (bid < 256) {
        int mb = bid >> 3, nb = bid & 7;
        sgemm32x64<DIMV, DIMV, true>(x, wq, g_q, mb * 32, nb * 64, smem);
    } else {
        int b = bid - 256;
        int d0 = (b & 15) * 32;
        int e0 = (b >> 4) * 32;
        float (*t)[33] = (float(*)[33])smem;
        int tx = threadIdx.x & 31, ty = threadIdx.x >> 5;   // 32 x 4
#pragma unroll
        for (int i = 0; i < 8; i++)
            t[ty + i * 4][tx] = wdown[(size_t)(e0 + ty + i * 4) * DIMV + d0 + tx];
        __syncthreads();
#pragma unroll
        for (int i = 0; i < 8; i++)
            g_wdT[(size_t)(d0 + ty + i * 4) * NUM_KEYS + e0 + tx] = t[tx][ty + i * 4];
    }
}

// ---------------------------------------------------------------------------
// K2: blocks 0..127 -> G2 (D = q @ wdT); 128..383 -> sim (32-token tiles).
// ---------------------------------------------------------------------------
#define SIM_SMEM_BYTES (DIM_KEY*NUM_KEYS*4 + DIM_KEY*32*4)

__global__ void __launch_bounds__(128)
k2_fused(const float* __restrict__ keys)
{
    __shared__ __align__(16) char smem[SIM_SMEM_BYTES > GEMM_SMEM_BYTES ?
                                       SIM_SMEM_BYTES : GEMM_SMEM_BYTES];
    int bid = blockIdx.x;
    int tid = threadIdx.x;   // 0..127

    if (bid < 128) {
        // G2: M=1024 (32 m-tiles), N=256 (4 n-tiles)
        int mb = bid >> 2, nb = bid & 3;
        sgemm32x64<NUM_KEYS, DIMV, false>(g_q, g_wdT, g_D, mb * 32, nb * 64, smem);
        return;
    }

    // sim: 256 blocks, each (32 tokens x 256 keys) for one head
    int b = bid - 128;
    int t0 = (b & 31) * 32;
    int h = b >> 5;

    float (*Ks)[NUM_KEYS] = (float(*)[NUM_KEYS])smem;
    float (*Qs)[32] = (float(*)[32])(smem + DIM_KEY * NUM_KEYS * 4);

    // load 2 keys per thread, transposed
#pragma unroll
    for (int kk = 0; kk < 2; kk++) {
        int key = tid + kk * 128;
        const float4* kp = reinterpret_cast<const float4*>(
            keys + (size_t)((h * NUM_KEYS + key) * 2) * DIM_KEY);
#pragma unroll
        for (int i = 0; i < 8; i++) {
            float4 f = kp[i];
            Ks[4 * i + 0][key] = f.x;
            Ks[4 * i + 1][key] = f.y;
            Ks[4 * i + 2][key] = f.z;
            Ks[4 * i + 3][key] = f.w;
        }
    }
    // load q slice transposed: token tl = tid&31, d-range (tid>>5)*8
    {
        int tl = tid & 31;
        int d0 = (tid >> 5) * 8;
        const float* qp = g_q + (size_t)(t0 + tl) * DIMV + h * DIM_KEY + d0;
        float4 f0 = *reinterpret_cast<const float4*>(qp);
        float4 f1 = *reinterpret_cast<const float4*>(qp + 4);
        Qs[d0 + 0][tl] = f0.x; Qs[d0 + 1][tl] = f0.y;
        Qs[d0 + 2][tl] = f0.z; Qs[d0 + 3][tl] = f0.w;
        Qs[d0 + 4][tl] = f1.x; Qs[d0 + 5][tl] = f1.y;
        Qs[d0 + 6][tl] = f1.z; Qs[d0 + 7][tl] = f1.w;
    }
    __syncthreads();

    int kg = tid & 15;   // 16 keys
    int tg = tid >> 4;   // 4 tokens (0..7)
    float acc[4][16];
#pragma unroll
    for (int i = 0; i < 4; i++)
#pragma unroll
        for (int j = 0; j < 16; j++) acc[i][j] = 0.0f;

#pragma unroll
    for (int d = 0; d < DIM_KEY; d++) {
        float4 qv = *reinterpret_cast<const float4*>(&Qs[d][tg * 4]);
        float q4[4] = {qv.x, qv.y, qv.z, qv.w};
        float kv[16];
#pragma unroll
        for (int jj = 0; jj < 4; jj++) {
            float4 kk = *reinterpret_cast<const float4*>(&Ks[d][kg * 16 + jj * 4]);
            kv[jj * 4 + 0] = kk.x; kv[jj * 4 + 1] = kk.y;
            kv[jj * 4 + 2] = kk.z; kv[jj * 4 + 3] = kk.w;
        }
#pragma unroll
        for (int i = 0; i < 4; i++)
#pragma unroll
            for (int j = 0; j < 16; j++) acc[i][j] += q4[i] * kv[j];
    }

#pragma unroll
    for (int i = 0; i < 4; i++) {
        int t = t0 + tg * 4 + i;
        float* op = g_sim + ((size_t)h * TOKENS + t) * NUM_KEYS + kg * 16;
#pragma unroll
        for (int jj = 0; jj < 4; jj++) {
            float4 f;
            f.x = acc[i][jj * 4 + 0]; f.y = acc[i][jj * 4 + 1];
            f.z = acc[i][jj * 4 + 2]; f.w = acc[i][jj * 4 + 3];
            *reinterpret_cast<float4*>(op + jj * 4) = f;
        }
    }
}

// ---------------------------------------------------------------------------
// K3: selection (deterministic cross-head merge, no atomics).
// ---------------------------------------------------------------------------
__device__ __forceinline__ float gelu_tanh(float x) {
    float x3 = x * x * x;
    float t = tanhf(0.7978845608028654f * (x + 0.044715f * x3));
    return 0.5f * x * (1.0f + t);
}

__device__ __forceinline__ void warp_top16(float* val, int lane,
                                           float* out_v, int* out_i)
{
#pragma unroll
    for (int r = 0; r < TOPK; r++) {
        float bv = val[0]; int bs = 0;
#pragma unroll
        for (int s = 1; s < 8; s++)
            if (val[s] > bv) { bv = val[s]; bs = s; }
        int bp = lane + (bs << 5);
#pragma unroll
        for (int off = 16; off > 0; off >>= 1) {
            float ov = __shfl_xor_sync(FULLMASK, bv, off);
            int   op = __shfl_xor_sync(FULLMASK, bp, off);
            if (ov > bv || (ov == bv && op < bp)) { bv = ov; bp = op; }
        }
        out_v[r] = bv;
        out_i[r] = bp;
        if ((bp & 31) == lane) {
            int ws = bp >> 5;
#pragma unroll
            for (int s = 0; s < 8; s++)
                if (s == ws) val[s] = -INFINITY;
        }
    }
}

__global__ void __launch_bounds__(256) select_kernel()
{
    int t = blockIdx.x;
    int tid = threadIdx.x;
    int w = tid >> 5;
    int lane = tid & 31;

    __shared__ float v0s[HEADS][TOPK];
    __shared__ float i0s[HEADS][TOPK];
    __shared__ int   pk_all[HEADS * TOPK];
    __shared__ float g_all[HEADS * TOPK];

    float val[8];
    {
        const float* simrow = g_sim + ((size_t)w * TOKENS + t) * NUM_KEYS;
#pragma unroll
        for (int s = 0; s < 8; s++)
            val[s] = simrow[lane + (s << 5)];
    }

    float v0[TOPK]; int i0[TOPK];
    warp_top16(val, lane, v0, i0);
    if (lane == 0) {
#pragma unroll
        for (int r = 0; r < TOPK; r++) {
            v0s[w][r] = v0[r];
            i0s[w][r] = (float)i0[r];
        }
    }
    __syncwarp();

    float val2[8];
#pragma unroll
    for (int s = 0; s < 8; s++) {
        int p = lane + (s << 5);
        val2[s] = v0s[w][p >> 4] + i0s[w][p & 15];
    }

    float scf[TOPK]; int pk[TOPK];
    warp_top16(val2, lane, scf, pk);

    float myscf = -INFINITY; int mypk = 0;
#pragma unroll
    for (int r = 0; r < TOPK; r++)
        if (lane == r) { myscf = scf[r]; mypk = pk[r]; }

    float m = scf[0];
#pragma unroll
    for (int r = 1; r < TOPK; r++) m = fmaxf(m, scf[r]);
    float mye = expf(myscf - m);
    float esum = mye;
#pragma unroll
    for (int off = 16; off > 0; off >>= 1)
        esum += __shfl_xor_sync(FULLMASK, esum, off);

    if (lane < TOPK) {
        float dv = g_D[(size_t)t * NUM_KEYS + mypk];
        float g = gelu_tanh(dv) * (mye / esum);
        pk_all[w * TOPK + lane] = mypk;
        g_all[w * TOPK + lane] = g;
    }
    __syncthreads();

    // deterministic merge: thread e sums entries with pk == e (fixed order)
    float s = 0.0f;
#pragma unroll
    for (int i = 0; i < HEADS * TOPK; i++) {
        s += (pk_all[i] == tid) ? g_all[i] : 0.0f;
    }
    g_S[(size_t)t * NUM_KEYS + tid] = s;
}

// ---------------------------------------------------------------------------
// K4: out = S @ wup[:256]
// ---------------------------------------------------------------------------
__global__ void __launch_bounds__(128)
k4_gemm(const float* __restrict__ wup, float* __restrict__ out)
{
    __shared__ __align__(16) char smem[GEMM_SMEM_BYTES];
    int bid = blockIdx.x;
    int mb = bid >> 3, nb = bid & 7;
    sgemm32x64<DIMV, NUM_KEYS, false>(g_S, wup, out, mb * 32, nb * 64, smem);
}

// ---------------------------------------------------------------------------
extern "C" void kernel_launch(void* const* d_in, const int* in_sizes, int n_in,
                              void* d_out, int out_size)
{
    const float* x     = (const float*)d_in[0];
    const float* w_q   = (const float*)d_in[1];
    const float* keys  = (const float*)d_in[2];
    const float* wdown = (const float*)d_in[3];
    const float* wup   = (const float*)d_in[4];
    float* out = (float*)d_out;

    k1_fused<<<384, 128>>>(x, w_q, wdown);
    k2_fused<<<384, 128>>>(keys);
    select_kernel<<<TOKENS, 256>>>();
    k4_gemm<<<256, 128>>>(wup, out);
}